// round 15
// baseline (speedup 1.0000x reference)
#include <cuda_runtime.h>
#include <cuda_fp16.h>
#include <stdint.h>
#include <math.h>

// Problem constants
#define S_    1024
#define E_    1024
#define H_    16
#define HD_   64
#define B_    4
#define BH_   (B_ * H_)          // 64
#define RELN_ (2 * S_ - 1)       // 2047
#define M_TOT (B_ * S_)          // 4096

// -------------------- scratch (device globals; no allocation) --------------------
__device__ __half g_Q[(size_t)BH_ * S_ * HD_];
__device__ __half g_K[(size_t)BH_ * S_ * HD_];
__device__ __half g_V[(size_t)BH_ * S_ * HD_];
__device__ __half g_rk[(size_t)RELN_ * HD_];

__device__ __half g_x[(size_t)M_TOT * E_];
__device__ __half g_w[(size_t)4 * E_ * E_];
__device__ __half g_c[(size_t)M_TOT * E_];
__device__ float  g_bias3[3 * E_];

// ==================================================================================
// helpers
// ==================================================================================
__device__ __forceinline__ uint32_t smem_u32(const void* p) {
    uint32_t a;
    asm("{ .reg .u64 t; cvta.to.shared.u64 t, %1; cvt.u32.u64 %0, t; }" : "=r"(a) : "l"(p));
    return a;
}
#define CP16(dst, src) \
    asm volatile("cp.async.cg.shared.global [%0], [%1], 16;" :: "r"(dst), "l"(src))
#define CP_COMMIT()   asm volatile("cp.async.commit_group;" ::: "memory")

__device__ __forceinline__ void mma16816(float* c, const uint32_t* a, const uint32_t* b) {
    asm volatile(
        "mma.sync.aligned.m16n8k16.row.col.f32.f16.f16.f32 "
        "{%0,%1,%2,%3},{%4,%5,%6,%7},{%8,%9},{%0,%1,%2,%3};"
        : "+f"(c[0]), "+f"(c[1]), "+f"(c[2]), "+f"(c[3])
        : "r"(a[0]), "r"(a[1]), "r"(a[2]), "r"(a[3]), "r"(b[0]), "r"(b[1]));
}
__device__ __forceinline__ void ldmx4(uint32_t* r, uint32_t a) {
    asm volatile("ldmatrix.sync.aligned.m8n8.x4.shared.b16 {%0,%1,%2,%3}, [%4];"
        : "=r"(r[0]), "=r"(r[1]), "=r"(r[2]), "=r"(r[3]) : "r"(a));
}
__device__ __forceinline__ void ldmx4t(uint32_t* r, uint32_t a) {
    asm volatile("ldmatrix.sync.aligned.m8n8.x4.trans.shared.b16 {%0,%1,%2,%3}, [%4];"
        : "=r"(r[0]), "=r"(r[1]), "=r"(r[2]), "=r"(r[3]) : "r"(a));
}

// ==================================================================================
// conv_all: x + Wq|Wk|Wv|Wo -> fp16 in one launch.
// ==================================================================================
#define XN4   (M_TOT * E_ / 4)          // 1048576
#define WN4   (E_ * E_ / 4)             // 262144

__global__ __launch_bounds__(256) void conv_all(
    const float* __restrict__ x,
    const float* __restrict__ Wq, const float* __restrict__ Wk,
    const float* __restrict__ Wv, const float* __restrict__ Wo,
    __half* __restrict__ xp, __half* __restrict__ wp)
{
    int i = blockIdx.x * blockDim.x + threadIdx.x;
    const float* src;
    __half* dst;
    int li;
    if (i < XN4) {
        src = x; dst = xp; li = i;
    } else {
        int j = i - XN4;
        if (j >= 4 * WN4) return;
        int t = j >> 18;
        li = j & (WN4 - 1);
        src = (t == 0) ? Wq : (t == 1) ? Wk : (t == 2) ? Wv : Wo;
        dst = wp + (size_t)t * (E_ * E_);
    }
    float4 v = reinterpret_cast<const float4*>(src)[li];
    __half2* dp = reinterpret_cast<__half2*>(dst);
    dp[li * 2 + 0] = __half2(__float2half_rn(v.x), __float2half_rn(v.y));
    dp[li * 2 + 1] = __half2(__float2half_rn(v.z), __float2half_rn(v.w));
}

// ==================================================================================
// HMMA GEMM — R15: B-operand pair loads via ldmx4 (4 instead of 8 LDSM per ks).
// ==================================================================================
#define TG_ROWB   80
#define TG_TILE   (128 * TG_ROWB)
#define TG_STAGE  (2 * TG_TILE)
#define TG_SMEM   (2 * TG_STAGE)           // 40960
#define TG_NKT    (E_ / 32)

__global__ __launch_bounds__(256, 2) void tc_gemm(
    const __half* __restrict__ A, const __half* __restrict__ Bw,
    const float* __restrict__ bias, float* __restrict__ Cf,
    __half* __restrict__ C0, __half* __restrict__ C1, __half* __restrict__ C2,
    int mode)
{
    extern __shared__ __align__(16) unsigned char dyn_smem[];
    const uint32_t sb = smem_u32(dyn_smem);
    const int tid  = threadIdx.x;
    const int wid  = tid >> 5;
    const int lane = tid & 31;
    const int wm   = wid >> 2;
    const int wn   = wid & 3;
    const int ql   = lane & 3;
    const int g    = lane >> 2;
    const int row0 = blockIdx.y * 128;
    const int col0 = blockIdx.x * 128;

    const __half* srcs[2] = { A + (size_t)row0 * E_, Bw + (size_t)col0 * E_ };

    auto load_stage = [&](int kt, int buf) {
        const int k0 = kt * 32;
        const uint32_t st = sb + buf * TG_STAGE;
        #pragma unroll
        for (int i = 0; i < 4; i++) {
            int id = tid + i * 256;
            int t  = id >> 9;
            int rem = id & 511;
            int r  = rem >> 2;
            int c  = rem & 3;
            const __half* src = srcs[t] + (size_t)r * E_ + k0 + c * 8;
            CP16(st + t * TG_TILE + r * TG_ROWB + c * 16, src);
        }
        CP_COMMIT();
    };

    load_stage(0, 0);
    load_stage(1, 1);

    float acc[4][4][4];
    #pragma unroll
    for (int i = 0; i < 4; i++)
        #pragma unroll
        for (int j = 0; j < 4; j++)
            #pragma unroll
            for (int v = 0; v < 4; v++) acc[i][j][v] = 0.f;

    const int a_radd = lane & 15;
    const int a_kadd = (lane >> 4) * 16;

    for (int kt = 0; kt < TG_NKT; kt++) {
        if (kt < TG_NKT - 1) asm volatile("cp.async.wait_group 1;" ::: "memory");
        else                 asm volatile("cp.async.wait_group 0;" ::: "memory");
        __syncthreads();

        const uint32_t st = sb + (kt & 1) * TG_STAGE;

        #pragma unroll
        for (int ks = 0; ks < 2; ks++) {
            uint32_t ah[4][4];
            #pragma unroll
            for (int i = 0; i < 4; i++) {
                uint32_t addr = st + (wm * 64 + i * 16 + a_radd) * TG_ROWB + ks * 32 + a_kadd;
                ldmx4(ah[i], addr);
            }
            #pragma unroll
            for (int j2 = 0; j2 < 2; j2++) {
                uint32_t br[4];
                uint32_t baddr = st + TG_TILE
                               + (wn * 32 + j2 * 16 + a_radd) * TG_ROWB + ks * 32 + a_kadd;
                ldmx4(br, baddr);
                uint32_t be[2] = { br[0], br[2] };
                uint32_t bo[2] = { br[1], br[3] };
                #pragma unroll
                for (int i = 0; i < 4; i++) mma16816(acc[i][2 * j2],     ah[i], be);
                #pragma unroll
                for (int i = 0; i < 4; i++) mma16816(acc[i][2 * j2 + 1], ah[i], bo);
            }
        }
        __syncthreads();
        if (kt + 2 < TG_NKT) load_stage(kt + 2, kt & 1);
    }

    __half* dst = (col0 < 1024) ? C0 : (col0 < 2048) ? C1 : C2;

    #pragma unroll
    for (int i = 0; i < 4; i++) {
        int m = row0 + wm * 64 + i * 16 + g;
        #pragma unroll
        for (int j = 0; j < 4; j++) {
            int n = col0 + wn * 32 + j * 8 + 2 * ql;
            float bx = bias[n], by = bias[n + 1];
            float o0 = acc[i][j][0] + bx, o1 = acc[i][j][1] + by;
            float o2 = acc[i][j][2] + bx, o3 = acc[i][j][3] + by;
            if (mode == 0) {
                *reinterpret_cast<float2*>(&Cf[(size_t)m * E_ + n])       = make_float2(o0, o1);
                *reinterpret_cast<float2*>(&Cf[(size_t)(m + 8) * E_ + n]) = make_float2(o2, o3);
            } else {
                int nloc = n & 1023;
                int hh = nloc >> 6, hd = nloc & 63;
                int bb = m >> 10, ss = m & 1023;
                int b2 = (m + 8) >> 10, s2 = (m + 8) & 1023;
                size_t i0 = (((size_t)(bb * H_ + hh)) * S_ + ss) * HD_ + hd;
                size_t i1 = (((size_t)(b2 * H_ + hh)) * S_ + s2) * HD_ + hd;
                *reinterpret_cast<__half2*>(&dst[i0]) =
                    __half2(__float2half_rn(o0), __float2half_rn(o1));
                *reinterpret_cast<__half2*>(&dst[i1]) =
                    __half2(__float2half_rn(o2), __float2half_rn(o3));
            }
        }
    }
}

// ==================================================================================
// rel_key -> fp16
// ==================================================================================
__global__ __launch_bounds__(256) void relkey_kernel(
    const float* __restrict__ rel_table, const float* __restrict__ Wp,
    __half* __restrict__ RK)
{
    __shared__ float w[64][65];
    __shared__ float rt[4][64];
    const int ty = threadIdx.x >> 6;
    const int t  = threadIdx.x & 63;
    const int p  = blockIdx.x * 4 + ty;
    for (int i = threadIdx.x; i < 4096; i += 256) w[i >> 6][i & 63] = Wp[i];
    if (p < RELN_) rt[ty][t] = rel_table[(size_t)p * 64 + t];
    __syncthreads();
    if (p >= RELN_) return;
    float s = 0.f;
    #pragma unroll
    for (int j = 0; j < 64; j++) s = fmaf(w[t][j], rt[ty][j], s);
    RK[(size_t)p * 64 + t] = __float2half_rn(s);
}

// ==================================================================================
// fused_attn — R15: P2 in fp16 (halves P2 smem traffic; smem 82.4KB),
// K/RK B-pairs via ldmx4, V pairs via ldmx4.trans (LDSM 48 -> 24 per iter-warp).
// Structure/pipeline identical to R14 (validated).
// ==================================================================================
#define FA_PITCH  144
#define FA_TILE   (64 * FA_PITCH)            // 9216
#define FA_OFF_Q  0                           // 1 tile
#define FA_OFF_K  (1 * FA_TILE)               // 2 stages
#define FA_OFF_V  (3 * FA_TILE)               // 2 stages
#define FA_OFF_RK (5 * FA_TILE)               // 2 stages
#define FA_OFF_P2 (7 * FA_TILE)               // 64512: 2 slots [64][68] fp16
#define FA_P2_SLOT (64 * 68 * 2)              // 8704
#define FA_OFF_PS (FA_OFF_P2 + 2 * FA_P2_SLOT) // 81920: PS[2][64]
#define FA_SMEM   (FA_OFF_PS + 2 * 64 * 4)    // 82432
#define FA_NKT    (S_ / 64)                   // 16
#define FA_CEXP   4.0f

__global__ __launch_bounds__(256, 2) void fused_attn(
    const __half* __restrict__ Q, const __half* __restrict__ K,
    const __half* __restrict__ V, const __half* __restrict__ RK,
    __half* __restrict__ C)
{
    extern __shared__ __align__(16) unsigned char dyn_smem[];
    const uint32_t sb = smem_u32(dyn_smem);
    const int tid  = threadIdx.x;
    const int wid  = tid >> 5;
    const int lane = tid & 31;
    const int ql   = lane & 3;
    const int gq   = lane >> 2;
    const int bh   = blockIdx.y;
    const int q0   = blockIdx.x * 64;
    const int pbase0 = (S_ - 64) - q0;

    const __half* Qsrc  = Q + ((size_t)bh * S_ + q0) * HD_;
    const __half* Kbase = K + (size_t)bh * S_ * HD_;
    const __half* Vbase = V + (size_t)bh * S_ * HD_;

    auto load_one = [&](uint32_t dst, const __half* src, int row0) {
        #pragma unroll
        for (int i = 0; i < 2; i++) {
            int id = tid + i * 256;
            int r = id >> 3, c = id & 7;
            CP16(dst + r * FA_PITCH + c * 16,
                 src + (size_t)(row0 + r) * HD_ + c * 8);
        }
    };

    __half* P2h0 = reinterpret_cast<__half*>(dyn_smem + FA_OFF_P2);
    __half* P2h1 = reinterpret_cast<__half*>(dyn_smem + FA_OFF_P2 + FA_P2_SLOT);
    float*  PS   = reinterpret_cast<float*>(dyn_smem + FA_OFF_PS);   // [2][64]

    // ---- prefetch: G0 = {Q, K0, V0, RKb0->s0, RKb1->s1}, G1 = {K1, V1} ONLY ----
    load_one(sb + FA_OFF_Q, Qsrc, 0);
    load_one(sb + FA_OFF_K, Kbase, 0);
    load_one(sb + FA_OFF_V, Vbase, 0);
    load_one(sb + FA_OFF_RK, RK, pbase0);
    load_one(sb + FA_OFF_RK + FA_TILE, RK, pbase0 + 64);
    CP_COMMIT();                                          // G0
    load_one(sb + FA_OFF_K + FA_TILE, Kbase, 64);
    load_one(sb + FA_OFF_V + FA_TILE, Vbase, 64);
    CP_COMMIT();                                          // G1

    asm volatile("cp.async.wait_group 0;" ::: "memory");
    __syncthreads();

    const int qw = wid >> 1;
    const int kh = wid & 1;
    const int a_radd = lane & 15;
    const int a_kadd = (lane >> 4) * 16;
    const int r0 = qw * 16 + gq;
    const int r1 = r0 + 8;

    // ---- bootstrap: P2 block 0 -> slot 0 ----
    {
        float pf[4][4];
        #pragma unroll
        for (int j = 0; j < 4; j++)
            #pragma unroll
            for (int v = 0; v < 4; v++) pf[j][v] = 0.f;
        #pragma unroll
        for (int ks = 0; ks < 4; ks++) {
            uint32_t ah[4];
            uint32_t aaddr = sb + FA_OFF_Q + (qw * 16 + a_radd) * FA_PITCH + ks * 32 + a_kadd;
            ldmx4(ah, aaddr);
            #pragma unroll
            for (int j2 = 0; j2 < 2; j2++) {
                uint32_t br[4];
                ldmx4(br, sb + FA_OFF_RK + (kh * 32 + j2 * 16 + a_radd) * FA_PITCH
                          + ks * 32 + a_kadd);
                uint32_t be[2] = { br[0], br[2] };
                uint32_t bo[2] = { br[1], br[3] };
                mma16816(pf[2 * j2],     ah, be);
                mma16816(pf[2 * j2 + 1], ah, bo);
            }
        }
        #pragma unroll
        for (int j = 0; j < 4; j++) {
            int col = kh * 32 + j * 8 + 2 * ql;
            *reinterpret_cast<__half2*>(&P2h0[r0 * 68 + col]) = __floats2half2_rn(pf[j][0], pf[j][1]);
            *reinterpret_cast<__half2*>(&P2h0[r1 * 68 + col]) = __floats2half2_rn(pf[j][2], pf[j][3]);
        }
    }
    __syncthreads();

    // safe: RK block 2 -> stage 0 (G2)
    load_one(sb + FA_OFF_RK, RK, pbase0 + 128);
    CP_COMMIT();

    float oacc[8][4];
    #pragma unroll
    for (int j = 0; j < 8; j++)
        #pragma unroll
        for (int v = 0; v < 4; v++) oacc[j][v] = 0.f;
    float ts0 = 0.f, ts1 = 0.f;

    for (int kt = 0; kt < FA_NKT; kt++) {
        if (kt < FA_NKT - 1) asm volatile("cp.async.wait_group 1;" ::: "memory");
        else                 asm volatile("cp.async.wait_group 0;" ::: "memory");
        __syncthreads();

        const uint32_t kst  = sb + FA_OFF_K  + (kt & 1) * FA_TILE;
        const uint32_t vst  = sb + FA_OFF_V  + (kt & 1) * FA_TILE;
        const uint32_t rkst = sb + FA_OFF_RK + ((kt + 1) & 1) * FA_TILE;
        __half* P2old = (kt & 1) ? P2h1 : P2h0;
        __half* P2new = (kt & 1) ? P2h0 : P2h1;

        // ---- phase A: content S (frags) + new P2 block (paired B loads) ----
        float sf[4][4], pf[4][4];
        #pragma unroll
        for (int j = 0; j < 4; j++)
            #pragma unroll
            for (int v = 0; v < 4; v++) { sf[j][v] = 0.f; pf[j][v] = 0.f; }

        #pragma unroll
        for (int ks = 0; ks < 4; ks++) {
            uint32_t ah[4];
            uint32_t aaddr = sb + FA_OFF_Q + (qw * 16 + a_radd) * FA_PITCH + ks * 32 + a_kadd;
            ldmx4(ah, aaddr);
            #pragma unroll
            for (int j2 = 0; j2 < 2; j2++) {
                uint32_t br[4];
                ldmx4(br, kst + (kh * 32 + j2 * 16 + a_radd) * FA_PITCH + ks * 32 + a_kadd);
                uint32_t be[2] = { br[0], br[2] };
                uint32_t bo[2] = { br[1], br[3] };
                mma16816(sf[2 * j2],     ah, be);
                mma16816(sf[2 * j2 + 1], ah, bo);
            }
            #pragma unroll
            for (int j2 = 0; j2 < 2; j2++) {
                uint32_t br[4];
                ldmx4(br, rkst + (kh * 32 + j2 * 16 + a_radd) * FA_PITCH + ks * 32 + a_kadd);
                uint32_t be[2] = { br[0], br[2] };
                uint32_t bo[2] = { br[1], br[3] };
                mma16816(pf[2 * j2],     ah, be);
                mma16816(pf[2 * j2 + 1], ah, bo);
            }
        }
        #pragma unroll
        for (int j = 0; j < 4; j++) {
            int col = kh * 32 + j * 8 + 2 * ql;
            *reinterpret_cast<__half2*>(&P2new[r0 * 68 + col]) = __floats2half2_rn(pf[j][0], pf[j][1]);
            *reinterpret_cast<__half2*>(&P2new[r1 * 68 + col]) = __floats2half2_rn(pf[j][2], pf[j][3]);
        }
        __syncthreads();

        // ---- phase C: fold shifted P2 (fp16 reads), exp, pack P fragments ----
        uint32_t pfrag[2][4];
        #pragma unroll
        for (int j = 0; j < 4; j++) {
            int k = kh * 32 + j * 8 + 2 * ql;
            int ra = 63 - r0 + k;
            float pa = __half2float((ra < 64)     ? P2old[r0 * 68 + ra]     : P2new[r0 * 68 + ra - 64]);
            float pb = __half2float((ra + 1 < 64) ? P2old[r0 * 68 + ra + 1] : P2new[r0 * 68 + ra - 63]);
            float p0 = __expf(fmaf(0.125f, sf[j][0] + pa, -FA_CEXP));
            float p1 = __expf(fmaf(0.125f, sf[j][1] + pb, -FA_CEXP));
            int rb = 63 - r1 + k;
            float pc = __half2float((rb < 64)     ? P2old[r1 * 68 + rb]     : P2new[r1 * 68 + rb - 64]);
            float pd = __half2float((rb + 1 < 64) ? P2old[r1 * 68 + rb + 1] : P2new[r1 * 68 + rb - 63]);
            float p2 = __expf(fmaf(0.125f, sf[j][2] + pc, -FA_CEXP));
            float p3 = __expf(fmaf(0.125f, sf[j][3] + pd, -FA_CEXP));
            ts0 += p0 + p1;
            ts1 += p2 + p3;
            __half2 h01 = __floats2half2_rn(p0, p1);
            __half2 h23 = __floats2half2_rn(p2, p3);
            pfrag[j >> 1][(j & 1) * 2 + 0] = *reinterpret_cast<uint32_t*>(&h01);
            pfrag[j >> 1][(j & 1) * 2 + 1] = *reinterpret_cast<uint32_t*>(&h23);
        }

        // ---- phase D: partial O += P(regs) @ V (paired trans loads) ----
        #pragma unroll
        for (int c = 0; c < 2; c++) {
            #pragma unroll
            for (int dj2 = 0; dj2 < 4; dj2++) {
                uint32_t vr[4];
                uint32_t vaddr = vst + (kh * 32 + c * 16 + a_radd) * FA_PITCH
                               + (dj2 * 2 + (lane >> 4)) * 16;
                ldmx4t(vr, vaddr);
                uint32_t ve[2] = { vr[0], vr[1] };
                uint32_t vo[2] = { vr[2], vr[3] };
                mma16816(oacc[2 * dj2],     pfrag[c], ve);
                mma16816(oacc[2 * dj2 + 1], pfrag[c], vo);
            }
        }
        __syncthreads();

        // ---- prefetch next: K/V kt+2, RK block kt+3 ----
        {
            bool any = false;
            if (kt + 2 < FA_NKT) {
                load_one(sb + FA_OFF_K + (kt & 1) * FA_TILE, Kbase, (kt + 2) * 64);
                load_one(sb + FA_OFF_V + (kt & 1) * FA_TILE, Vbase, (kt + 2) * 64);
                any = true;
            }
            if (kt + 3 <= FA_NKT) {
                load_one(sb + FA_OFF_RK + ((kt + 3) & 1) * FA_TILE, RK,
                         pbase0 + (kt + 3) * 64);
                any = true;
            }
            if (any) CP_COMMIT();
        }
    }

    // ---- epilogue: reduce l; sum kh-partial O through dead P2 region; write ctx ----
    ts0 += __shfl_xor_sync(0xffffffffu, ts0, 1);
    ts0 += __shfl_xor_sync(0xffffffffu, ts0, 2);
    ts1 += __shfl_xor_sync(0xffffffffu, ts1, 1);
    ts1 += __shfl_xor_sync(0xffffffffu, ts1, 2);
    if (ql == 0) { PS[kh * 64 + r0] = ts0; PS[kh * 64 + r1] = ts1; }

    float* Ored = reinterpret_cast<float*>(dyn_smem + FA_OFF_P2);  // 64x68 fp32 = 17408B (exact fit)
    if (kh == 0) {
        #pragma unroll
        for (int dj = 0; dj < 8; dj++) {
            int col = dj * 8 + 2 * ql;
            *reinterpret_cast<float2*>(&Ored[r0 * 68 + col]) = make_float2(oacc[dj][0], oacc[dj][1]);
            *reinterpret_cast<float2*>(&Ored[r1 * 68 + col]) = make_float2(oacc[dj][2], oacc[dj][3]);
        }
    }
    __syncthreads();
    if (kh == 1) {
        const int bb = bh >> 4;
        const int hh = bh & 15;
        float il0 = 1.0f / (PS[r0] + PS[64 + r0]);
        float il1 = 1.0f / (PS[r1] + PS[64 + r1]);
        int q = q0 + r0;
        #pragma unroll
        for (int dj = 0; dj < 8; dj++) {
            int col = dj * 8 + 2 * ql;
            float o0 = (oacc[dj][0] + Ored[r0 * 68 + col])     * il0;
            float o1 = (oacc[dj][1] + Ored[r0 * 68 + col + 1]) * il0;
            float o2 = (oacc[dj][2] + Ored[r1 * 68 + col])     * il1;
            float o3 = (oacc[dj][3] + Ored[r1 * 68 + col + 1]) * il1;
            int e = hh * HD_ + col;
            size_t i0 = ((size_t)bb * S_ + q) * E_ + e;
            size_t i1 = ((size_t)bb * S_ + q + 8) * E_ + e;
            *reinterpret_cast<__half2*>(&C[i0]) =
                __half2(__float2half_rn(o0), __float2half_rn(o1));
            *reinterpret_cast<__half2*>(&C[i1]) =
                __half2(__float2half_rn(o2), __float2half_rn(o3));
        }
    }
}

// ==================================================================================
// Launch
// ==================================================================================
extern "C" void kernel_launch(void* const* d_in, const int* in_sizes, int n_in,
                              void* d_out, int out_size)
{
    const float* x   = (const float*)d_in[0];
    const float* Wq  = (const float*)d_in[1];
    const float* bq  = (const float*)d_in[2];
    const float* Wk  = (const float*)d_in[3];
    const float* bk  = (const float*)d_in[4];
    const float* Wv  = (const float*)d_in[5];
    const float* bv  = (const float*)d_in[6];
    const float* Wo  = (const float*)d_in[7];
    const float* bo  = (const float*)d_in[8];
    const float* Wp  = (const float*)d_in[9];
    const float* rel = (const float*)d_in[10];
    float* out = (float*)d_out;

    __half *qp, *kp, *vp, *rkp, *xp, *wp, *cp;
    float* b3;
    cudaGetSymbolAddress((void**)&qp,  g_Q);
    cudaGetSymbolAddress((void**)&kp,  g_K);
    cudaGetSymbolAddress((void**)&vp,  g_V);
    cudaGetSymbolAddress((void**)&rkp, g_rk);
    cudaGetSymbolAddress((void**)&xp,  g_x);
    cudaGetSymbolAddress((void**)&wp,  g_w);
    cudaGetSymbolAddress((void**)&cp,  g_c);
    cudaGetSymbolAddress((void**)&b3,  g_bias3);

    cudaFuncSetAttribute(tc_gemm,    cudaFuncAttributeMaxDynamicSharedMemorySize, TG_SMEM);
    cudaFuncSetAttribute(fused_attn, cudaFuncAttributeMaxDynamicSharedMemorySize, FA_SMEM);

    const size_t WSZ = (size_t)E_ * E_;

    cudaMemcpyAsync(b3,        bq, E_ * sizeof(float), cudaMemcpyDeviceToDevice);
    cudaMemcpyAsync(b3 + E_,   bk, E_ * sizeof(float), cudaMemcpyDeviceToDevice);
    cudaMemcpyAsync(b3 + 2*E_, bv, E_ * sizeof(float), cudaMemcpyDeviceToDevice);

    // [0] conv everything
    conv_all<<<(XN4 + 4 * WN4 + 255) / 256, 256>>>(x, Wq, Wk, Wv, Wo, xp, wp);
    // [1] relkey
    relkey_kernel<<<(RELN_ + 3) / 4, 256>>>(rel, Wp, rkp);
    // [2] tc_gemm QKV fused
    tc_gemm<<<dim3(3 * E_ / 128, M_TOT / 128), 256, TG_SMEM>>>(
        xp, wp, b3, nullptr, qp, kp, vp, 1);
    // [3] fused attention
    fused_attn<<<dim3(S_ / 64, BH_), 256, FA_SMEM>>>(qp, kp, vp, rkp, cp);
    // [4] tc_gemm final
    tc_gemm<<<dim3(E_ / 128, M_TOT / 128), 256, TG_SMEM>>>(
        cp, wp + 3 * WSZ, bo, out, nullptr, nullptr, nullptr, 0);
}

// round 16
// speedup vs baseline: 1.0677x; 1.0677x over previous
#include <cuda_runtime.h>
#include <cuda_fp16.h>
#include <stdint.h>
#include <math.h>

// Problem constants
#define S_    1024
#define E_    1024
#define H_    16
#define HD_   64
#define B_    4
#define BH_   (B_ * H_)          // 64
#define RELN_ (2 * S_ - 1)       // 2047
#define M_TOT (B_ * S_)          // 4096

// -------------------- scratch (device globals; no allocation) --------------------
__device__ __half g_Q[(size_t)BH_ * S_ * HD_];
__device__ __half g_K[(size_t)BH_ * S_ * HD_];
__device__ __half g_V[(size_t)BH_ * S_ * HD_];
__device__ __half g_rk[(size_t)RELN_ * HD_];

__device__ __half g_x[(size_t)M_TOT * E_];
__device__ __half g_w[(size_t)4 * E_ * E_];
__device__ __half g_c[(size_t)M_TOT * E_];
__device__ float  g_bias3[3 * E_];

// ==================================================================================
// helpers
// ==================================================================================
__device__ __forceinline__ uint32_t smem_u32(const void* p) {
    uint32_t a;
    asm("{ .reg .u64 t; cvta.to.shared.u64 t, %1; cvt.u32.u64 %0, t; }" : "=r"(a) : "l"(p));
    return a;
}
#define CP16(dst, src) \
    asm volatile("cp.async.cg.shared.global [%0], [%1], 16;" :: "r"(dst), "l"(src))
#define CP_COMMIT()   asm volatile("cp.async.commit_group;" ::: "memory")

__device__ __forceinline__ void mma16816(float* c, const uint32_t* a, const uint32_t* b) {
    asm volatile(
        "mma.sync.aligned.m16n8k16.row.col.f32.f16.f16.f32 "
        "{%0,%1,%2,%3},{%4,%5,%6,%7},{%8,%9},{%0,%1,%2,%3};"
        : "+f"(c[0]), "+f"(c[1]), "+f"(c[2]), "+f"(c[3])
        : "r"(a[0]), "r"(a[1]), "r"(a[2]), "r"(a[3]), "r"(b[0]), "r"(b[1]));
}
__device__ __forceinline__ void ldmx4(uint32_t* r, uint32_t a) {
    asm volatile("ldmatrix.sync.aligned.m8n8.x4.shared.b16 {%0,%1,%2,%3}, [%4];"
        : "=r"(r[0]), "=r"(r[1]), "=r"(r[2]), "=r"(r[3]) : "r"(a));
}
__device__ __forceinline__ void ldmx2(uint32_t* r, uint32_t a) {
    asm volatile("ldmatrix.sync.aligned.m8n8.x2.shared.b16 {%0,%1}, [%2];"
        : "=r"(r[0]), "=r"(r[1]) : "r"(a));
}
__device__ __forceinline__ void ldmx4t(uint32_t* r, uint32_t a) {
    asm volatile("ldmatrix.sync.aligned.m8n8.x4.trans.shared.b16 {%0,%1,%2,%3}, [%4];"
        : "=r"(r[0]), "=r"(r[1]), "=r"(r[2]), "=r"(r[3]) : "r"(a));
}

// ==================================================================================
// conv_all: x + Wq|Wk|Wv|Wo -> fp16 in one launch.
// ==================================================================================
#define XN4   (M_TOT * E_ / 4)          // 1048576
#define WN4   (E_ * E_ / 4)             // 262144

__global__ __launch_bounds__(256) void conv_all(
    const float* __restrict__ x,
    const float* __restrict__ Wq, const float* __restrict__ Wk,
    const float* __restrict__ Wv, const float* __restrict__ Wo,
    __half* __restrict__ xp, __half* __restrict__ wp)
{
    int i = blockIdx.x * blockDim.x + threadIdx.x;
    const float* src;
    __half* dst;
    int li;
    if (i < XN4) {
        src = x; dst = xp; li = i;
    } else {
        int j = i - XN4;
        if (j >= 4 * WN4) return;
        int t = j >> 18;
        li = j & (WN4 - 1);
        src = (t == 0) ? Wq : (t == 1) ? Wk : (t == 2) ? Wv : Wo;
        dst = wp + (size_t)t * (E_ * E_);
    }
    float4 v = reinterpret_cast<const float4*>(src)[li];
    __half2* dp = reinterpret_cast<__half2*>(dst);
    dp[li * 2 + 0] = __half2(__float2half_rn(v.x), __float2half_rn(v.y));
    dp[li * 2 + 1] = __half2(__float2half_rn(v.z), __float2half_rn(v.w));
}

// ==================================================================================
// HMMA GEMM — reverted to R14 form (ldmx2 B loads; 80B pitch conflict-free).
// ==================================================================================
#define TG_ROWB   80
#define TG_TILE   (128 * TG_ROWB)
#define TG_STAGE  (2 * TG_TILE)
#define TG_SMEM   (2 * TG_STAGE)           // 40960
#define TG_NKT    (E_ / 32)

__global__ __launch_bounds__(256, 2) void tc_gemm(
    const __half* __restrict__ A, const __half* __restrict__ Bw,
    const float* __restrict__ bias, float* __restrict__ Cf,
    __half* __restrict__ C0, __half* __restrict__ C1, __half* __restrict__ C2,
    int mode)
{
    extern __shared__ __align__(16) unsigned char dyn_smem[];
    const uint32_t sb = smem_u32(dyn_smem);
    const int tid  = threadIdx.x;
    const int wid  = tid >> 5;
    const int lane = tid & 31;
    const int wm   = wid >> 2;
    const int wn   = wid & 3;
    const int ql   = lane & 3;
    const int g    = lane >> 2;
    const int row0 = blockIdx.y * 128;
    const int col0 = blockIdx.x * 128;

    const __half* srcs[2] = { A + (size_t)row0 * E_, Bw + (size_t)col0 * E_ };

    auto load_stage = [&](int kt, int buf) {
        const int k0 = kt * 32;
        const uint32_t st = sb + buf * TG_STAGE;
        #pragma unroll
        for (int i = 0; i < 4; i++) {
            int id = tid + i * 256;
            int t  = id >> 9;
            int rem = id & 511;
            int r  = rem >> 2;
            int c  = rem & 3;
            const __half* src = srcs[t] + (size_t)r * E_ + k0 + c * 8;
            CP16(st + t * TG_TILE + r * TG_ROWB + c * 16, src);
        }
        CP_COMMIT();
    };

    load_stage(0, 0);
    load_stage(1, 1);

    float acc[4][4][4];
    #pragma unroll
    for (int i = 0; i < 4; i++)
        #pragma unroll
        for (int j = 0; j < 4; j++)
            #pragma unroll
            for (int v = 0; v < 4; v++) acc[i][j][v] = 0.f;

    const int a_radd = lane & 15;
    const int a_kadd = (lane >> 4) * 16;
    const int b_radd = lane & 7;
    const int b_kadd = ((lane >> 3) & 1) * 16;

    for (int kt = 0; kt < TG_NKT; kt++) {
        if (kt < TG_NKT - 1) asm volatile("cp.async.wait_group 1;" ::: "memory");
        else                 asm volatile("cp.async.wait_group 0;" ::: "memory");
        __syncthreads();

        const uint32_t st = sb + (kt & 1) * TG_STAGE;

        #pragma unroll
        for (int ks = 0; ks < 2; ks++) {
            uint32_t ah[4][4];
            #pragma unroll
            for (int i = 0; i < 4; i++) {
                uint32_t addr = st + (wm * 64 + i * 16 + a_radd) * TG_ROWB + ks * 32 + a_kadd;
                ldmx4(ah[i], addr);
            }
            #pragma unroll
            for (int j = 0; j < 4; j++) {
                uint32_t baddr = st + TG_TILE
                               + (wn * 32 + j * 8 + b_radd) * TG_ROWB + ks * 32 + b_kadd;
                uint32_t bhf[2];
                ldmx2(bhf, baddr);
                #pragma unroll
                for (int i = 0; i < 4; i++) mma16816(acc[i][j], ah[i], bhf);
            }
        }
        __syncthreads();
        if (kt + 2 < TG_NKT) load_stage(kt + 2, kt & 1);
    }

    __half* dst = (col0 < 1024) ? C0 : (col0 < 2048) ? C1 : C2;

    #pragma unroll
    for (int i = 0; i < 4; i++) {
        int m = row0 + wm * 64 + i * 16 + g;
        #pragma unroll
        for (int j = 0; j < 4; j++) {
            int n = col0 + wn * 32 + j * 8 + 2 * ql;
            float bx = bias[n], by = bias[n + 1];
            float o0 = acc[i][j][0] + bx, o1 = acc[i][j][1] + by;
            float o2 = acc[i][j][2] + bx, o3 = acc[i][j][3] + by;
            if (mode == 0) {
                *reinterpret_cast<float2*>(&Cf[(size_t)m * E_ + n])       = make_float2(o0, o1);
                *reinterpret_cast<float2*>(&Cf[(size_t)(m + 8) * E_ + n]) = make_float2(o2, o3);
            } else {
                int nloc = n & 1023;
                int hh = nloc >> 6, hd = nloc & 63;
                int bb = m >> 10, ss = m & 1023;
                int b2 = (m + 8) >> 10, s2 = (m + 8) & 1023;
                size_t i0 = (((size_t)(bb * H_ + hh)) * S_ + ss) * HD_ + hd;
                size_t i1 = (((size_t)(b2 * H_ + hh)) * S_ + s2) * HD_ + hd;
                *reinterpret_cast<__half2*>(&dst[i0]) =
                    __half2(__float2half_rn(o0), __float2half_rn(o1));
                *reinterpret_cast<__half2*>(&dst[i1]) =
                    __half2(__float2half_rn(o2), __float2half_rn(o3));
            }
        }
    }
}

// ==================================================================================
// rel_key -> fp16
// ==================================================================================
__global__ __launch_bounds__(256) void relkey_kernel(
    const float* __restrict__ rel_table, const float* __restrict__ Wp,
    __half* __restrict__ RK)
{
    __shared__ float w[64][65];
    __shared__ float rt[4][64];
    const int ty = threadIdx.x >> 6;
    const int t  = threadIdx.x & 63;
    const int p  = blockIdx.x * 4 + ty;
    for (int i = threadIdx.x; i < 4096; i += 256) w[i >> 6][i & 63] = Wp[i];
    if (p < RELN_) rt[ty][t] = rel_table[(size_t)p * 64 + t];
    __syncthreads();
    if (p >= RELN_) return;
    float s = 0.f;
    #pragma unroll
    for (int j = 0; j < 64; j++) s = fmaf(w[t][j], rt[ty][j], s);
    RK[(size_t)p * 64 + t] = __float2half_rn(s);
}

// ==================================================================================
// fused_attn — R15 form kept verbatim (measured 126.8us):
// P2 fp16, K/RK paired ldmx4, V paired ldmx4.trans, register-resident P.
// ==================================================================================
#define FA_PITCH  144
#define FA_TILE   (64 * FA_PITCH)            // 9216
#define FA_OFF_Q  0
#define FA_OFF_K  (1 * FA_TILE)
#define FA_OFF_V  (3 * FA_TILE)
#define FA_OFF_RK (5 * FA_TILE)
#define FA_OFF_P2 (7 * FA_TILE)              // 64512: 2 slots [64][68] fp16
#define FA_P2_SLOT (64 * 68 * 2)             // 8704
#define FA_OFF_PS (FA_OFF_P2 + 2 * FA_P2_SLOT) // 81920
#define FA_SMEM   (FA_OFF_PS + 2 * 64 * 4)   // 82432
#define FA_NKT    (S_ / 64)                  // 16
#define FA_CEXP   4.0f

__global__ __launch_bounds__(256, 2) void fused_attn(
    const __half* __restrict__ Q, const __half* __restrict__ K,
    const __half* __restrict__ V, const __half* __restrict__ RK,
    __half* __restrict__ C)
{
    extern __shared__ __align__(16) unsigned char dyn_smem[];
    const uint32_t sb = smem_u32(dyn_smem);
    const int tid  = threadIdx.x;
    const int wid  = tid >> 5;
    const int lane = tid & 31;
    const int ql   = lane & 3;
    const int gq   = lane >> 2;
    const int bh   = blockIdx.y;
    const int q0   = blockIdx.x * 64;
    const int pbase0 = (S_ - 64) - q0;

    const __half* Qsrc  = Q + ((size_t)bh * S_ + q0) * HD_;
    const __half* Kbase = K + (size_t)bh * S_ * HD_;
    const __half* Vbase = V + (size_t)bh * S_ * HD_;

    auto load_one = [&](uint32_t dst, const __half* src, int row0) {
        #pragma unroll
        for (int i = 0; i < 2; i++) {
            int id = tid + i * 256;
            int r = id >> 3, c = id & 7;
            CP16(dst + r * FA_PITCH + c * 16,
                 src + (size_t)(row0 + r) * HD_ + c * 8);
        }
    };

    __half* P2h0 = reinterpret_cast<__half*>(dyn_smem + FA_OFF_P2);
    __half* P2h1 = reinterpret_cast<__half*>(dyn_smem + FA_OFF_P2 + FA_P2_SLOT);
    float*  PS   = reinterpret_cast<float*>(dyn_smem + FA_OFF_PS);

    // ---- prefetch: G0 = {Q, K0, V0, RKb0->s0, RKb1->s1}, G1 = {K1, V1} ONLY ----
    load_one(sb + FA_OFF_Q, Qsrc, 0);
    load_one(sb + FA_OFF_K, Kbase, 0);
    load_one(sb + FA_OFF_V, Vbase, 0);
    load_one(sb + FA_OFF_RK, RK, pbase0);
    load_one(sb + FA_OFF_RK + FA_TILE, RK, pbase0 + 64);
    CP_COMMIT();                                          // G0
    load_one(sb + FA_OFF_K + FA_TILE, Kbase, 64);
    load_one(sb + FA_OFF_V + FA_TILE, Vbase, 64);
    CP_COMMIT();                                          // G1

    asm volatile("cp.async.wait_group 0;" ::: "memory");
    __syncthreads();

    const int qw = wid >> 1;
    const int kh = wid & 1;
    const int a_radd = lane & 15;
    const int a_kadd = (lane >> 4) * 16;
    const int r0 = qw * 16 + gq;
    const int r1 = r0 + 8;

    // ---- bootstrap: P2 block 0 -> slot 0 ----
    {
        float pf[4][4];
        #pragma unroll
        for (int j = 0; j < 4; j++)
            #pragma unroll
            for (int v = 0; v < 4; v++) pf[j][v] = 0.f;
        #pragma unroll
        for (int ks = 0; ks < 4; ks++) {
            uint32_t ah[4];
            uint32_t aaddr = sb + FA_OFF_Q + (qw * 16 + a_radd) * FA_PITCH + ks * 32 + a_kadd;
            ldmx4(ah, aaddr);
            #pragma unroll
            for (int j2 = 0; j2 < 2; j2++) {
                uint32_t br[4];
                ldmx4(br, sb + FA_OFF_RK + (kh * 32 + j2 * 16 + a_radd) * FA_PITCH
                          + ks * 32 + a_kadd);
                uint32_t be[2] = { br[0], br[2] };
                uint32_t bo[2] = { br[1], br[3] };
                mma16816(pf[2 * j2],     ah, be);
                mma16816(pf[2 * j2 + 1], ah, bo);
            }
        }
        #pragma unroll
        for (int j = 0; j < 4; j++) {
            int col = kh * 32 + j * 8 + 2 * ql;
            *reinterpret_cast<__half2*>(&P2h0[r0 * 68 + col]) = __floats2half2_rn(pf[j][0], pf[j][1]);
            *reinterpret_cast<__half2*>(&P2h0[r1 * 68 + col]) = __floats2half2_rn(pf[j][2], pf[j][3]);
        }
    }
    __syncthreads();

    // safe: RK block 2 -> stage 0 (G2)
    load_one(sb + FA_OFF_RK, RK, pbase0 + 128);
    CP_COMMIT();

    float oacc[8][4];
    #pragma unroll
    for (int j = 0; j < 8; j++)
        #pragma unroll
        for (int v = 0; v < 4; v++) oacc[j][v] = 0.f;
    float ts0 = 0.f, ts1 = 0.f;

    for (int kt = 0; kt < FA_NKT; kt++) {
        if (kt < FA_NKT - 1) asm volatile("cp.async.wait_group 1;" ::: "memory");
        else                 asm volatile("cp.async.wait_group 0;" ::: "memory");
        __syncthreads();

        const uint32_t kst  = sb + FA_OFF_K  + (kt & 1) * FA_TILE;
        const uint32_t vst  = sb + FA_OFF_V  + (kt & 1) * FA_TILE;
        const uint32_t rkst = sb + FA_OFF_RK + ((kt + 1) & 1) * FA_TILE;
        __half* P2old = (kt & 1) ? P2h1 : P2h0;
        __half* P2new = (kt & 1) ? P2h0 : P2h1;

        // ---- phase A: content S (frags) + new P2 block (paired B loads) ----
        float sf[4][4], pf[4][4];
        #pragma unroll
        for (int j = 0; j < 4; j++)
            #pragma unroll
            for (int v = 0; v < 4; v++) { sf[j][v] = 0.f; pf[j][v] = 0.f; }

        #pragma unroll
        for (int ks = 0; ks < 4; ks++) {
            uint32_t ah[4];
            uint32_t aaddr = sb + FA_OFF_Q + (qw * 16 + a_radd) * FA_PITCH + ks * 32 + a_kadd;
            ldmx4(ah, aaddr);
            #pragma unroll
            for (int j2 = 0; j2 < 2; j2++) {
                uint32_t br[4];
                ldmx4(br, kst + (kh * 32 + j2 * 16 + a_radd) * FA_PITCH + ks * 32 + a_kadd);
                uint32_t be[2] = { br[0], br[2] };
                uint32_t bo[2] = { br[1], br[3] };
                mma16816(sf[2 * j2],     ah, be);
                mma16816(sf[2 * j2 + 1], ah, bo);
            }
            #pragma unroll
            for (int j2 = 0; j2 < 2; j2++) {
                uint32_t br[4];
                ldmx4(br, rkst + (kh * 32 + j2 * 16 + a_radd) * FA_PITCH + ks * 32 + a_kadd);
                uint32_t be[2] = { br[0], br[2] };
                uint32_t bo[2] = { br[1], br[3] };
                mma16816(pf[2 * j2],     ah, be);
                mma16816(pf[2 * j2 + 1], ah, bo);
            }
        }
        #pragma unroll
        for (int j = 0; j < 4; j++) {
            int col = kh * 32 + j * 8 + 2 * ql;
            *reinterpret_cast<__half2*>(&P2new[r0 * 68 + col]) = __floats2half2_rn(pf[j][0], pf[j][1]);
            *reinterpret_cast<__half2*>(&P2new[r1 * 68 + col]) = __floats2half2_rn(pf[j][2], pf[j][3]);
        }
        __syncthreads();

        // ---- phase C: fold shifted P2 (fp16 reads), exp, pack P fragments ----
        uint32_t pfrag[2][4];
        #pragma unroll
        for (int j = 0; j < 4; j++) {
            int k = kh * 32 + j * 8 + 2 * ql;
            int ra = 63 - r0 + k;
            float pa = __half2float((ra < 64)     ? P2old[r0 * 68 + ra]     : P2new[r0 * 68 + ra - 64]);
            float pb = __half2float((ra + 1 < 64) ? P2old[r0 * 68 + ra + 1] : P2new[r0 * 68 + ra - 63]);
            float p0 = __expf(fmaf(0.125f, sf[j][0] + pa, -FA_CEXP));
            float p1 = __expf(fmaf(0.125f, sf[j][1] + pb, -FA_CEXP));
            int rb = 63 - r1 + k;
            float pc = __half2float((rb < 64)     ? P2old[r1 * 68 + rb]     : P2new[r1 * 68 + rb - 64]);
            float pd = __half2float((rb + 1 < 64) ? P2old[r1 * 68 + rb + 1] : P2new[r1 * 68 + rb - 63]);
            float p2 = __expf(fmaf(0.125f, sf[j][2] + pc, -FA_CEXP));
            float p3 = __expf(fmaf(0.125f, sf[j][3] + pd, -FA_CEXP));
            ts0 += p0 + p1;
            ts1 += p2 + p3;
            __half2 h01 = __floats2half2_rn(p0, p1);
            __half2 h23 = __floats2half2_rn(p2, p3);
            pfrag[j >> 1][(j & 1) * 2 + 0] = *reinterpret_cast<uint32_t*>(&h01);
            pfrag[j >> 1][(j & 1) * 2 + 1] = *reinterpret_cast<uint32_t*>(&h23);
        }

        // ---- phase D: partial O += P(regs) @ V (paired trans loads) ----
        #pragma unroll
        for (int c = 0; c < 2; c++) {
            #pragma unroll
            for (int dj2 = 0; dj2 < 4; dj2++) {
                uint32_t vr[4];
                uint32_t vaddr = vst + (kh * 32 + c * 16 + a_radd) * FA_PITCH
                               + (dj2 * 2 + (lane >> 4)) * 16;
                ldmx4t(vr, vaddr);
                uint32_t ve[2] = { vr[0], vr[1] };
                uint32_t vo[2] = { vr[2], vr[3] };
                mma16816(oacc[2 * dj2],     pfrag[c], ve);
                mma16816(oacc[2 * dj2 + 1], pfrag[c], vo);
            }
        }
        __syncthreads();

        // ---- prefetch next: K/V kt+2, RK block kt+3 ----
        {
            bool any = false;
            if (kt + 2 < FA_NKT) {
                load_one(sb + FA_OFF_K + (kt & 1) * FA_TILE, Kbase, (kt + 2) * 64);
                load_one(sb + FA_OFF_V + (kt & 1) * FA_TILE, Vbase, (kt + 2) * 64);
                any = true;
            }
            if (kt + 3 <= FA_NKT) {
                load_one(sb + FA_OFF_RK + ((kt + 3) & 1) * FA_TILE, RK,
                         pbase0 + (kt + 3) * 64);
                any = true;
            }
            if (any) CP_COMMIT();
        }
    }

    // ---- epilogue: reduce l; sum kh-partial O through dead P2 region; write ctx ----
    ts0 += __shfl_xor_sync(0xffffffffu, ts0, 1);
    ts0 += __shfl_xor_sync(0xffffffffu, ts0, 2);
    ts1 += __shfl_xor_sync(0xffffffffu, ts1, 1);
    ts1 += __shfl_xor_sync(0xffffffffu, ts1, 2);
    if (ql == 0) { PS[kh * 64 + r0] = ts0; PS[kh * 64 + r1] = ts1; }

    float* Ored = reinterpret_cast<float*>(dyn_smem + FA_OFF_P2);  // 64x68 fp32 (exact fit)
    if (kh == 0) {
        #pragma unroll
        for (int dj = 0; dj < 8; dj++) {
            int col = dj * 8 + 2 * ql;
            *reinterpret_cast<float2*>(&Ored[r0 * 68 + col]) = make_float2(oacc[dj][0], oacc[dj][1]);
            *reinterpret_cast<float2*>(&Ored[r1 * 68 + col]) = make_float2(oacc[dj][2], oacc[dj][3]);
        }
    }
    __syncthreads();
    if (kh == 1) {
        const int bb = bh >> 4;
        const int hh = bh & 15;
        float il0 = 1.0f / (PS[r0] + PS[64 + r0]);
        float il1 = 1.0f / (PS[r1] + PS[64 + r1]);
        int q = q0 + r0;
        #pragma unroll
        for (int dj = 0; dj < 8; dj++) {
            int col = dj * 8 + 2 * ql;
            float o0 = (oacc[dj][0] + Ored[r0 * 68 + col])     * il0;
            float o1 = (oacc[dj][1] + Ored[r0 * 68 + col + 1]) * il0;
            float o2 = (oacc[dj][2] + Ored[r1 * 68 + col])     * il1;
            float o3 = (oacc[dj][3] + Ored[r1 * 68 + col + 1]) * il1;
            int e = hh * HD_ + col;
            size_t i0 = ((size_t)bb * S_ + q) * E_ + e;
            size_t i1 = ((size_t)bb * S_ + q + 8) * E_ + e;
            *reinterpret_cast<__half2*>(&C[i0]) =
                __half2(__float2half_rn(o0), __float2half_rn(o1));
            *reinterpret_cast<__half2*>(&C[i1]) =
                __half2(__float2half_rn(o2), __float2half_rn(o3));
        }
    }
}

// ==================================================================================
// Launch
// ==================================================================================
extern "C" void kernel_launch(void* const* d_in, const int* in_sizes, int n_in,
                              void* d_out, int out_size)
{
    const float* x   = (const float*)d_in[0];
    const float* Wq  = (const float*)d_in[1];
    const float* bq  = (const float*)d_in[2];
    const float* Wk  = (const float*)d_in[3];
    const float* bk  = (const float*)d_in[4];
    const float* Wv  = (const float*)d_in[5];
    const float* bv  = (const float*)d_in[6];
    const float* Wo  = (const float*)d_in[7];
    const float* bo  = (const float*)d_in[8];
    const float* Wp  = (const float*)d_in[9];
    const float* rel = (const float*)d_in[10];
    float* out = (float*)d_out;

    __half *qp, *kp, *vp, *rkp, *xp, *wp, *cp;
    float* b3;
    cudaGetSymbolAddress((void**)&qp,  g_Q);
    cudaGetSymbolAddress((void**)&kp,  g_K);
    cudaGetSymbolAddress((void**)&vp,  g_V);
    cudaGetSymbolAddress((void**)&rkp, g_rk);
    cudaGetSymbolAddress((void**)&xp,  g_x);
    cudaGetSymbolAddress((void**)&wp,  g_w);
    cudaGetSymbolAddress((void**)&cp,  g_c);
    cudaGetSymbolAddress((void**)&b3,  g_bias3);

    cudaFuncSetAttribute(tc_gemm,    cudaFuncAttributeMaxDynamicSharedMemorySize, TG_SMEM);
    cudaFuncSetAttribute(fused_attn, cudaFuncAttributeMaxDynamicSharedMemorySize, FA_SMEM);

    const size_t WSZ = (size_t)E_ * E_;

    cudaMemcpyAsync(b3,        bq, E_ * sizeof(float), cudaMemcpyDeviceToDevice);
    cudaMemcpyAsync(b3 + E_,   bk, E_ * sizeof(float), cudaMemcpyDeviceToDevice);
    cudaMemcpyAsync(b3 + 2*E_, bv, E_ * sizeof(float), cudaMemcpyDeviceToDevice);

    // [0] conv everything
    conv_all<<<(XN4 + 4 * WN4 + 255) / 256, 256>>>(x, Wq, Wk, Wv, Wo, xp, wp);
    // [1] relkey
    relkey_kernel<<<(RELN_ + 3) / 4, 256>>>(rel, Wp, rkp);
    // [2] tc_gemm QKV fused
    tc_gemm<<<dim3(3 * E_ / 128, M_TOT / 128), 256, TG_SMEM>>>(
        xp, wp, b3, nullptr, qp, kp, vp, 1);
    // [3] fused attention
    fused_attn<<<dim3(S_ / 64, BH_), 256, FA_SMEM>>>(qp, kp, vp, rkp, cp);
    // [4] tc_gemm final
    tc_gemm<<<dim3(E_ / 128, M_TOT / 128), 256, TG_SMEM>>>(
        cp, wp + 3 * WSZ, bo, out, nullptr, nullptr, nullptr, 0);
}